// round 11
// baseline (speedup 1.0000x reference)
#include <cuda_runtime.h>
#include <cuda_bf16.h>
#include <math.h>
#include <stdint.h>

// ---------------------------------------------------------------------------
// 25-pt (radius-4, 3-axis) wave stencil, 10 scan steps (first trivial),
// then loss = mean((out-ref)^2), max_abs = max|out-ref|.
// R11: dual-plane body, ONE barrier + ONE wait per 2 planes. cp.async ring
// of SIX buffers, fills at distance +4 issued AFTER the body's barrier
// (race-free: fill targets were consumed at body I-1; barrier separates).
// 10-register rotated z-queue. float4 compute, 4 x-pts/thread.
// ---------------------------------------------------------------------------

#define NN 192
#define PLANE (NN * NN)
#define VOL (NN * NN * NN)

#define TXT 16
#define TY 8
#define NTHR (TXT * TY)          // 128
#define SPANX (TXT * 4)          // 64 x-points per block
#define ZC 16
#define R  4

#define TILE_H (TY + 2 * R)      // 16
#define TILE_WU (SPANX + 2 * R)  // 72 floats used
#define TILE_W 80                // padded row stride
#define FW4 (TILE_WU / 4)        // 18 float4 per row
#define NSLOT (TILE_H * FW4)     // 288 fill slots
#define NBUF 6

#define C0 ((float)(-205.0 / 72.0 / 400.0))
#define C1 ((float)(8.0 / 5.0 / 400.0))
#define C2 ((float)(-1.0 / 5.0 / 400.0))
#define C3 ((float)(8.0 / 315.0 / 400.0))
#define C4 ((float)(-1.0 / 560.0 / 400.0))

__device__ float g_bufA[VOL];
__device__ float g_bufB[VOL];
__device__ double g_sum;
__device__ unsigned int g_maxbits;

__global__ void init_accum_kernel() {
    g_sum = 0.0;
    g_maxbits = 0u;
}

__device__ __forceinline__ float4 ldg4(const float* p) {
    return *reinterpret_cast<const float4*>(p);
}
__device__ __forceinline__ float4 ldcs4(const float* p) {
    float4 v;
    asm volatile("ld.global.cs.v4.f32 {%0,%1,%2,%3}, [%4];"
                 : "=f"(v.x), "=f"(v.y), "=f"(v.z), "=f"(v.w) : "l"(p));
    return v;
}
__device__ __forceinline__ float ldcs1(const float* p) {
    float v;
    asm volatile("ld.global.cs.f32 %0, [%1];" : "=f"(v) : "l"(p));
    return v;
}

__device__ __forceinline__ void fill_plane_async(
    uint32_t sbase, const float* gplane, const int* goff, const int* sidx) {
#pragma unroll
    for (int k = 0; k < 3; k++) {
        if (sidx[k] >= 0) {
            const float* srcp = (goff[k] >= 0) ? (gplane + goff[k]) : gplane;
            int sz = (goff[k] >= 0) ? 16 : 0;
            asm volatile("cp.async.cg.shared.global [%0], [%1], 16, %2;"
                         :: "r"(sbase + (uint32_t)sidx[k] * 4u), "l"(srcp), "r"(sz));
        }
    }
    asm volatile("cp.async.commit_group;" ::: "memory");
}

// 25-pt laplacian for one plane from tile t + 9 z-queue values.
__device__ __forceinline__ float4 lap25(
    const float (&t)[TILE_H][TILE_W], int sx, int syc,
    const float4& qm4, const float4& qm3, const float4& qm2, const float4& qm1,
    const float4& qc,
    const float4& qp1, const float4& qp2, const float4& qp3, const float4& qp4) {

    float xs[12];
#pragma unroll
    for (int j = 0; j < 3; j++) {
        float4 v = *reinterpret_cast<const float4*>(&t[syc][sx - 4 + 4 * j]);
        xs[4 * j + 0] = v.x;
        xs[4 * j + 1] = v.y;
        xs[4 * j + 2] = v.z;
        xs[4 * j + 3] = v.w;
    }

    float lap[4];
    {
        const float* q4 = &qc.x;
#pragma unroll
        for (int p = 0; p < 4; p++) lap[p] = (3.0f * C0) * q4[p];
    }
    {
        float4 ym = *reinterpret_cast<const float4*>(&t[syc - 1][sx]);
        float4 yp = *reinterpret_cast<const float4*>(&t[syc + 1][sx]);
        const float* a = &ym.x; const float* b = &yp.x;
        const float* m = &qm1.x; const float* pl = &qp1.x;
#pragma unroll
        for (int p = 0; p < 4; p++)
            lap[p] += C1 * (m[p] + pl[p] + a[p] + b[p] + xs[p + 3] + xs[p + 5]);
    }
    {
        float4 ym = *reinterpret_cast<const float4*>(&t[syc - 2][sx]);
        float4 yp = *reinterpret_cast<const float4*>(&t[syc + 2][sx]);
        const float* a = &ym.x; const float* b = &yp.x;
        const float* m = &qm2.x; const float* pl = &qp2.x;
#pragma unroll
        for (int p = 0; p < 4; p++)
            lap[p] += C2 * (m[p] + pl[p] + a[p] + b[p] + xs[p + 2] + xs[p + 6]);
    }
    {
        float4 ym = *reinterpret_cast<const float4*>(&t[syc - 3][sx]);
        float4 yp = *reinterpret_cast<const float4*>(&t[syc + 3][sx]);
        const float* a = &ym.x; const float* b = &yp.x;
        const float* m = &qm3.x; const float* pl = &qp3.x;
#pragma unroll
        for (int p = 0; p < 4; p++)
            lap[p] += C3 * (m[p] + pl[p] + a[p] + b[p] + xs[p + 1] + xs[p + 7]);
    }
    {
        float4 ym = *reinterpret_cast<const float4*>(&t[syc - 4][sx]);
        float4 yp = *reinterpret_cast<const float4*>(&t[syc + 4][sx]);
        const float* a = &ym.x; const float* b = &yp.x;
        const float* m = &qm4.x; const float* pl = &qp4.x;
#pragma unroll
        for (int p = 0; p < 4; p++)
            lap[p] += C4 * (m[p] + pl[p] + a[p] + b[p] + xs[p] + xs[p + 8]);
    }
    return make_float4(lap[0], lap[1], lap[2], lap[3]);
}

// Dual-plane body for planes (z, z+1).
// Order: wait tiles -> barrier -> issue fills z+4,z+5 + all LDGs -> compute.
template <bool FINAL>
__device__ __forceinline__ void body2(
    const float* __restrict__ cur, const float* __restrict__ prev,
    const float* __restrict__ vp, const float* __restrict__ src,
    float* __restrict__ out, const float* __restrict__ ref,
    const float (&cons0)[TILE_H][TILE_W], const float (&cons1)[TILE_H][TILE_W],
    uint32_t fb0, uint32_t fb1,
    int z, bool hasprev,
    const int* goff, const int* sidx, int col,
    float4& Q0, float4& Q1, float4& Q2, float4& Q3, float4& Q4,
    float4& Q5, float4& Q6, float4& Q7, float4& Q8, float4& Q9,
    int sx, int syc,
    double& acc_s, float& acc_m) {

    const int idx0 = z * PLANE + col;
    const int idx1 = idx0 + PLANE;

    // ---- tiles (z, z+1) ready; prior consumers done ----
    asm volatile("cp.async.wait_group 2;" ::: "memory");
    __syncthreads();

    // ---- now safe: issue fills for z+4, z+5 (targets consumed 1 body ago) ----
    {
        int zf = z + 4; if (zf > NN - 1) zf = NN - 1;
        fill_plane_async(fb0, cur + zf * PLANE, goff, sidx);
        zf = z + 5; if (zf > NN - 1) zf = NN - 1;
        fill_plane_async(fb1, cur + zf * PLANE, goff, sidx);
    }
    // q-heads for the NEXT body (planes z+6, z+7)
    float4 qh0, qh1;
    {
        int zp = z + 6;
        qh0 = (zp < NN) ? ldg4(&cur[zp * PLANE + col]) : make_float4(0.f, 0.f, 0.f, 0.f);
        zp = z + 7;
        qh1 = (zp < NN) ? ldg4(&cur[zp * PLANE + col]) : make_float4(0.f, 0.f, 0.f, 0.f);
    }
    // pointwise operands for both planes (burst)
    const float4 pv0 = hasprev ? ldg4(&prev[idx0]) : make_float4(0.f, 0.f, 0.f, 0.f);
    const float4 pv1 = hasprev ? ldg4(&prev[idx1]) : make_float4(0.f, 0.f, 0.f, 0.f);
    const float4 vv0 = ldg4(&vp[idx0]);
    const float4 vv1 = ldg4(&vp[idx1]);
    const float4 sv0 = ldcs4(&src[idx0]);
    const float4 sv1 = ldcs4(&src[idx1]);

    // ---- plane z ----
    {
        float4 lp = lap25(cons0, sx, syc, Q0, Q1, Q2, Q3, Q4, Q5, Q6, Q7, Q8);
        float4 upd;
        const float* qc = &Q4.x;
        const float* pvp = &pv0.x; const float* vvp = &vv0.x; const float* svp = &sv0.x;
        const float* lpp = &lp.x; float* u = &upd.x;
#pragma unroll
        for (int p = 0; p < 4; p++)
            u[p] = 2.0f * qc[p] - pvp[p] + vvp[p] * lpp[p] + svp[p];
        if (FINAL) {
#pragma unroll
            for (int p = 0; p < 4; p++) {
                out[idx0 + p] = u[p];
                float e = u[p] - ldcs1(&ref[idx0 + p]);
                acc_s += (double)e * (double)e;
                acc_m = fmaxf(acc_m, fabsf(e));
            }
        } else {
            *reinterpret_cast<float4*>(&out[idx0]) = upd;
        }
    }

    // ---- plane z+1 ----
    {
        float4 lp = lap25(cons1, sx, syc, Q1, Q2, Q3, Q4, Q5, Q6, Q7, Q8, Q9);
        float4 upd;
        const float* qc = &Q5.x;
        const float* pvp = &pv1.x; const float* vvp = &vv1.x; const float* svp = &sv1.x;
        const float* lpp = &lp.x; float* u = &upd.x;
#pragma unroll
        for (int p = 0; p < 4; p++)
            u[p] = 2.0f * qc[p] - pvp[p] + vvp[p] * lpp[p] + svp[p];
        if (FINAL) {
#pragma unroll
            for (int p = 0; p < 4; p++) {
                out[idx1 + p] = u[p];
                float e = u[p] - ldcs1(&ref[idx1 + p]);
                acc_s += (double)e * (double)e;
                acc_m = fmaxf(acc_m, fabsf(e));
            }
        } else {
            *reinterpret_cast<float4*>(&out[idx1]) = upd;
        }
    }

    // rotate: outgoing registers take the prefetched heads
    Q0 = qh0;   // plane z+6
    Q1 = qh1;   // plane z+7
}

template <bool FINAL>
__global__ void __launch_bounds__(NTHR, 6)
step_kernel(const float* __restrict__ cur,
            const float* __restrict__ prev,
            const float* __restrict__ vp,
            const float* __restrict__ src,
            float* __restrict__ out,
            const float* __restrict__ ref) {
    __shared__ float sp[NBUF][TILE_H][TILE_W];   // 6-deep ring (30 KB)

    const int tx = threadIdx.x;
    const int ty = threadIdx.y;
    const int x0 = blockIdx.x * SPANX;
    const int y0 = blockIdx.y * TY;
    const int z0 = blockIdx.z * ZC;
    const int gx = x0 + 4 * tx;
    const int gy = y0 + ty;
    const int tid = ty * TXT + tx;
    const int col = gy * NN + gx;

    int goff[3], sidx[3];
#pragma unroll
    for (int k = 0; k < 3; k++) {
        int i = tid + k * NTHR;
        if (i < NSLOT) {
            int sy = i / FW4;
            int sxx = i - sy * FW4;
            int yy = y0 - R + sy;
            int xx = x0 - R + 4 * sxx;
            sidx[k] = sy * TILE_W + 4 * sxx;
            goff[k] = (xx >= 0 && xx + 3 < NN && yy >= 0 && yy < NN)
                          ? (yy * NN + xx) : -1;
        } else {
            sidx[k] = -1;
            goff[k] = -1;
        }
    }

    uint32_t sb6[NBUF];
#pragma unroll
    for (int b = 0; b < NBUF; b++)
        sb6[b] = (uint32_t)__cvta_generic_to_shared(&sp[b][0][0]);

    // Prologue: fills for planes z0..z0+3 into bufs 0..3 (4 commit groups)
    fill_plane_async(sb6[0], cur + z0 * PLANE, goff, sidx);
    fill_plane_async(sb6[1], cur + (z0 + 1) * PLANE, goff, sidx);
    fill_plane_async(sb6[2], cur + (z0 + 2) * PLANE, goff, sidx);
    fill_plane_async(sb6[3], cur + (z0 + 3) * PLANE, goff, sidx);

    // z-queue: 10 named registers, planes z0-4 .. z0+5
    float4 r0, r1, r2, r3, r4, r5, r6, r7, r8, r9;
    {
        float4* rr[10] = {&r0, &r1, &r2, &r3, &r4, &r5, &r6, &r7, &r8, &r9};
#pragma unroll
        for (int k = 0; k < 10; k++) {
            int gz = z0 - R + k;
            *rr[k] = (gz >= 0 && gz < NN) ? ldg4(&cur[gz * PLANE + col])
                                          : make_float4(0.f, 0.f, 0.f, 0.f);
        }
    }

    const bool hasprev = (prev != nullptr);
    const int sx = R + 4 * tx;
    const int syc = ty + R;

    double acc_s = 0.0;
    float acc_m = 0.0f;

    // 8 dual-plane bodies (ZC=16). Consume bufs (2I)%6,(2I+1)%6;
    // fill bufs (2I+4)%6,(2I+5)%6 (planes z+4,z+5). Queue rotates +2/body.
#define PB2(I, a, b, cc, d, e, f, g, h, i, j)                                 \
    body2<FINAL>(cur, prev, vp, src, out, ref,                                \
                 sp[(2 * (I)) % 6], sp[(2 * (I) + 1) % 6],                    \
                 sb6[(2 * (I) + 4) % 6], sb6[(2 * (I) + 5) % 6],              \
                 z0 + 2 * (I), hasprev, goff, sidx, col,                      \
                 r##a, r##b, r##cc, r##d, r##e, r##f, r##g, r##h, r##i, r##j, \
                 sx, syc, acc_s, acc_m)

    PB2(0, 0, 1, 2, 3, 4, 5, 6, 7, 8, 9);
    PB2(1, 2, 3, 4, 5, 6, 7, 8, 9, 0, 1);
    PB2(2, 4, 5, 6, 7, 8, 9, 0, 1, 2, 3);
    PB2(3, 6, 7, 8, 9, 0, 1, 2, 3, 4, 5);
    PB2(4, 8, 9, 0, 1, 2, 3, 4, 5, 6, 7);
    PB2(5, 0, 1, 2, 3, 4, 5, 6, 7, 8, 9);
    PB2(6, 2, 3, 4, 5, 6, 7, 8, 9, 0, 1);
    PB2(7, 4, 5, 6, 7, 8, 9, 0, 1, 2, 3);
#undef PB2

    if (FINAL) {
#pragma unroll
        for (int o = 16; o > 0; o >>= 1) {
            acc_s += __shfl_down_sync(0xFFFFFFFFu, acc_s, o);
            acc_m = fmaxf(acc_m, __shfl_down_sync(0xFFFFFFFFu, acc_m, o));
        }
        __shared__ double ss[4];
        __shared__ float sm[4];
        int lane = tid & 31;
        int w = tid >> 5;
        if (lane == 0) { ss[w] = acc_s; sm[w] = acc_m; }
        __syncthreads();
        if (w == 0) {
            acc_s = (lane < 4) ? ss[lane] : 0.0;
            acc_m = (lane < 4) ? sm[lane] : 0.0f;
#pragma unroll
            for (int o = 2; o > 0; o >>= 1) {
                acc_s += __shfl_down_sync(0xFFFFFFFFu, acc_s, o);
                acc_m = fmaxf(acc_m, __shfl_down_sync(0xFFFFFFFFu, acc_m, o));
            }
            if (lane == 0) {
                atomicAdd(&g_sum, acc_s);
                atomicMax(&g_maxbits, __float_as_uint(acc_m));
            }
        }
    }
}

__global__ void finalize_kernel(float* d_out, int n) {
    d_out[0] = (float)(g_sum / (double)n);
    d_out[n + 1] = __uint_as_float(g_maxbits);
}

extern "C" void kernel_launch(void* const* d_in, const int* in_sizes, int n_in,
                              void* d_out, int out_size) {
    const float* vp  = (const float*)d_in[0];
    const float* src = (const float*)d_in[1];
    const float* ref = (const float*)d_in[2];

    static float* bufA = nullptr;
    static float* bufB = nullptr;
    if (!bufA) {
        cudaGetSymbolAddress((void**)&bufA, g_bufA);
        cudaGetSymbolAddress((void**)&bufB, g_bufB);
    }

    const bool has_scalars = (out_size >= VOL + 2);
    float* outp = has_scalars ? ((float*)d_out + 1) : (float*)d_out;

    dim3 blk(TXT, TY);
    dim3 grid(NN / SPANX, NN / TY, NN / ZC);   // (3, 24, 12) = 864 blocks

    init_accum_kernel<<<1, 1>>>();

    const float* s0 = src;

    step_kernel<false><<<grid, blk>>>(s0,   nullptr, vp, src + (size_t)1 * VOL, bufA, nullptr);
    step_kernel<false><<<grid, blk>>>(bufA, s0,      vp, src + (size_t)2 * VOL, bufB, nullptr);
    step_kernel<false><<<grid, blk>>>(bufB, bufA,    vp, src + (size_t)3 * VOL, bufA, nullptr);
    step_kernel<false><<<grid, blk>>>(bufA, bufB,    vp, src + (size_t)4 * VOL, bufB, nullptr);
    step_kernel<false><<<grid, blk>>>(bufB, bufA,    vp, src + (size_t)5 * VOL, bufA, nullptr);
    step_kernel<false><<<grid, blk>>>(bufA, bufB,    vp, src + (size_t)6 * VOL, bufB, nullptr);
    step_kernel<false><<<grid, blk>>>(bufB, bufA,    vp, src + (size_t)7 * VOL, bufA, nullptr);
    step_kernel<false><<<grid, blk>>>(bufA, bufB,    vp, src + (size_t)8 * VOL, bufB, nullptr);
    step_kernel<true><<<grid, blk>>>(bufB, bufA,     vp, src + (size_t)9 * VOL, outp, ref);

    if (has_scalars) {
        finalize_kernel<<<1, 1>>>((float*)d_out, VOL);
    }
}

// round 12
// speedup vs baseline: 1.1504x; 1.1504x over previous
#include <cuda_runtime.h>
#include <cuda_bf16.h>
#include <math.h>
#include <stdint.h>

// ---------------------------------------------------------------------------
// 25-pt (radius-4, 3-axis) wave stencil, 10 scan steps (first trivial),
// then loss = mean((out-ref)^2), max_abs = max|out-ref|.
// R12: ALL DRAM-latency loads async. Two cp.async rings (3 deep each):
//  - stencil tile ring (plane z-tiles with halo)
//  - pointwise ring (prev/vp/src interior quads, 1 float4/thread/field)
// Fills issued after the body barrier for plane z+2; one commit per body;
// wait_group 1. In-body global traffic: only q-head prefetch (1-body slack)
// and the output store. float4 compute, register-rotated z-queue (R9 style).
// ---------------------------------------------------------------------------

#define NN 192
#define PLANE (NN * NN)
#define VOL (NN * NN * NN)

#define TXT 16
#define TY 8
#define NTHR (TXT * TY)          // 128
#define SPANX (TXT * 4)          // 64 x-points per block
#define ZC 16
#define R  4

#define TILE_H (TY + 2 * R)      // 16
#define TILE_WU (SPANX + 2 * R)  // 72 floats used
#define TILE_W 80                // padded row stride
#define FW4 (TILE_WU / 4)        // 18 float4 per row
#define NSLOT (TILE_H * FW4)     // 288 fill slots
#define NBUF 3

#define C0 ((float)(-205.0 / 72.0 / 400.0))
#define C1 ((float)(8.0 / 5.0 / 400.0))
#define C2 ((float)(-1.0 / 5.0 / 400.0))
#define C3 ((float)(8.0 / 315.0 / 400.0))
#define C4 ((float)(-1.0 / 560.0 / 400.0))

__device__ float g_bufA[VOL];
__device__ float g_bufB[VOL];
__device__ double g_sum;
__device__ unsigned int g_maxbits;

__global__ void init_accum_kernel() {
    g_sum = 0.0;
    g_maxbits = 0u;
}

__device__ __forceinline__ float4 ldg4(const float* p) {
    return *reinterpret_cast<const float4*>(p);
}
__device__ __forceinline__ float ldcs1(const float* p) {
    float v;
    asm volatile("ld.global.cs.f32 %0, [%1];" : "=f"(v) : "l"(p));
    return v;
}

// Stencil tile fill (cp.async, NO commit — caller commits)
__device__ __forceinline__ void fill_plane(
    uint32_t sbase, const float* gplane, const int* goff, const int* sidx) {
#pragma unroll
    for (int k = 0; k < 3; k++) {
        if (sidx[k] >= 0) {
            const float* srcp = (goff[k] >= 0) ? (gplane + goff[k]) : gplane;
            int sz = (goff[k] >= 0) ? 16 : 0;
            asm volatile("cp.async.cg.shared.global [%0], [%1], 16, %2;"
                         :: "r"(sbase + (uint32_t)sidx[k] * 4u), "l"(srcp), "r"(sz));
        }
    }
}

// Pointwise fill: prev/vp/src interior quads for one plane (NO commit).
// Layout in slot: [field 0: prev][field 1: vp][field 2: src], float4/thread.
__device__ __forceinline__ void fill_pw(
    uint32_t pwbase, const float* prev, const float* vp, const float* src,
    int idx, bool hasprev, int tid) {
    uint32_t d = pwbase + (uint32_t)tid * 16u;
    if (hasprev) {
        asm volatile("cp.async.cg.shared.global [%0], [%1], 16;"
                     :: "r"(d), "l"(prev + idx));
    }
    asm volatile("cp.async.cg.shared.global [%0], [%1], 16;"
                 :: "r"(d + NTHR * 16u), "l"(vp + idx));
    asm volatile("cp.async.cg.shared.global [%0], [%1], 16;"
                 :: "r"(d + 2u * NTHR * 16u), "l"(src + idx));
}

// 25-pt laplacian for one plane from tile t + 9 z-queue values.
__device__ __forceinline__ float4 lap25(
    const float (&t)[TILE_H][TILE_W], int sx, int syc,
    const float4& qm4, const float4& qm3, const float4& qm2, const float4& qm1,
    const float4& qc,
    const float4& qp1, const float4& qp2, const float4& qp3, const float4& qp4) {

    float xs[12];
#pragma unroll
    for (int j = 0; j < 3; j++) {
        float4 v = *reinterpret_cast<const float4*>(&t[syc][sx - 4 + 4 * j]);
        xs[4 * j + 0] = v.x;
        xs[4 * j + 1] = v.y;
        xs[4 * j + 2] = v.z;
        xs[4 * j + 3] = v.w;
    }

    float lap[4];
    {
        const float* q4 = &qc.x;
#pragma unroll
        for (int p = 0; p < 4; p++) lap[p] = (3.0f * C0) * q4[p];
    }
    {
        float4 ym = *reinterpret_cast<const float4*>(&t[syc - 1][sx]);
        float4 yp = *reinterpret_cast<const float4*>(&t[syc + 1][sx]);
        const float* a = &ym.x; const float* b = &yp.x;
        const float* m = &qm1.x; const float* pl = &qp1.x;
#pragma unroll
        for (int p = 0; p < 4; p++)
            lap[p] += C1 * (m[p] + pl[p] + a[p] + b[p] + xs[p + 3] + xs[p + 5]);
    }
    {
        float4 ym = *reinterpret_cast<const float4*>(&t[syc - 2][sx]);
        float4 yp = *reinterpret_cast<const float4*>(&t[syc + 2][sx]);
        const float* a = &ym.x; const float* b = &yp.x;
        const float* m = &qm2.x; const float* pl = &qp2.x;
#pragma unroll
        for (int p = 0; p < 4; p++)
            lap[p] += C2 * (m[p] + pl[p] + a[p] + b[p] + xs[p + 2] + xs[p + 6]);
    }
    {
        float4 ym = *reinterpret_cast<const float4*>(&t[syc - 3][sx]);
        float4 yp = *reinterpret_cast<const float4*>(&t[syc + 3][sx]);
        const float* a = &ym.x; const float* b = &yp.x;
        const float* m = &qm3.x; const float* pl = &qp3.x;
#pragma unroll
        for (int p = 0; p < 4; p++)
            lap[p] += C3 * (m[p] + pl[p] + a[p] + b[p] + xs[p + 1] + xs[p + 7]);
    }
    {
        float4 ym = *reinterpret_cast<const float4*>(&t[syc - 4][sx]);
        float4 yp = *reinterpret_cast<const float4*>(&t[syc + 4][sx]);
        const float* a = &ym.x; const float* b = &yp.x;
        const float* m = &qm4.x; const float* pl = &qp4.x;
#pragma unroll
        for (int p = 0; p < 4; p++)
            lap[p] += C4 * (m[p] + pl[p] + a[p] + b[p] + xs[p] + xs[p + 8]);
    }
    return make_float4(lap[0], lap[1], lap[2], lap[3]);
}

// Body for plane z:
//  wait_group 1 -> barrier -> fill S(z+2)+PW(z+2), commit -> q-head LDG(z+5)
//  -> LDS pv/vv/sv -> compute -> store. Outgoing qm4 takes the new head.
template <bool FINAL>
__device__ __forceinline__ void plane_body(
    const float* __restrict__ cur, const float* __restrict__ prev,
    const float* __restrict__ vp, const float* __restrict__ src,
    float* __restrict__ out, const float* __restrict__ ref,
    const float (&consume)[TILE_H][TILE_W],
    const float* pwcons,          // this body's pointwise slot (floats)
    uint32_t fill_sb, uint32_t fill_pb,
    int z, bool hasprev,
    const int* goff, const int* sidx, int col, int tid,
    float4& qm4, float4& qm3, float4& qm2, float4& qm1, float4& qc,
    float4& qp1, float4& qp2, float4& qp3, float4& qp4,
    int sx, int syc,
    double& acc_s, float& acc_m) {

    const int idx = z * PLANE + col;

    // tile(z) + pw(z) complete; all warps done with body z-1's compute
    asm volatile("cp.async.wait_group 1;" ::: "memory");
    __syncthreads();

    // fills for plane z+2 (slot consumed at body z-1 -> safe post-barrier)
    {
        int zf = z + 2; if (zf > NN - 1) zf = NN - 1;
        fill_plane(fill_sb, cur + zf * PLANE, goff, sidx);
        fill_pw(fill_pb, prev, vp, src, zf * PLANE + col, hasprev, tid);
        asm volatile("cp.async.commit_group;" ::: "memory");
    }

    // q-head prefetch for NEXT body (plane z+5)
    float4 qn;
    {
        int zp = z + 5;
        qn = (zp < NN) ? ldg4(&cur[zp * PLANE + col]) : make_float4(0.f, 0.f, 0.f, 0.f);
    }

    // pointwise operands from smem (29-cycle LDS, fully pipelined)
    const float4 pv = hasprev
        ? *reinterpret_cast<const float4*>(pwcons + 4 * tid)
        : make_float4(0.f, 0.f, 0.f, 0.f);
    const float4 vv = *reinterpret_cast<const float4*>(pwcons + 4 * (NTHR + tid));
    const float4 sv = *reinterpret_cast<const float4*>(pwcons + 4 * (2 * NTHR + tid));

    float4 lp = lap25(consume, sx, syc, qm4, qm3, qm2, qm1, qc, qp1, qp2, qp3, qp4);

    float4 upd;
    {
        const float* q4 = &qc.x;
        const float* pvp = &pv.x; const float* vvp = &vv.x; const float* svp = &sv.x;
        const float* lpp = &lp.x; float* u = &upd.x;
#pragma unroll
        for (int p = 0; p < 4; p++)
            u[p] = 2.0f * q4[p] - pvp[p] + vvp[p] * lpp[p] + svp[p];
    }

    if (FINAL) {
        const float* u = &upd.x;
#pragma unroll
        for (int p = 0; p < 4; p++) {
            out[idx + p] = u[p];
            float e = u[p] - ldcs1(&ref[idx + p]);
            acc_s += (double)e * (double)e;
            acc_m = fmaxf(acc_m, fabsf(e));
        }
    } else {
        *reinterpret_cast<float4*>(&out[idx]) = upd;
    }

    qm4 = qn;   // rotation: becomes next body's qp4
}

template <bool FINAL>
__global__ void __launch_bounds__(NTHR, 6)
step_kernel(const float* __restrict__ cur,
            const float* __restrict__ prev,
            const float* __restrict__ vp,
            const float* __restrict__ src,
            float* __restrict__ out,
            const float* __restrict__ ref) {
    __shared__ float sp[NBUF][TILE_H][TILE_W];        // 3 x 5120B stencil tiles
    __shared__ float pwr[NBUF][3 * NTHR * 4];         // 3 x 6144B pointwise slots

    const int tx = threadIdx.x;
    const int ty = threadIdx.y;
    const int x0 = blockIdx.x * SPANX;
    const int y0 = blockIdx.y * TY;
    const int z0 = blockIdx.z * ZC;
    const int gx = x0 + 4 * tx;
    const int gy = y0 + ty;
    const int tid = ty * TXT + tx;
    const int col = gy * NN + gx;

    int goff[3], sidx[3];
#pragma unroll
    for (int k = 0; k < 3; k++) {
        int i = tid + k * NTHR;
        if (i < NSLOT) {
            int sy = i / FW4;
            int sxx = i - sy * FW4;
            int yy = y0 - R + sy;
            int xx = x0 - R + 4 * sxx;
            sidx[k] = sy * TILE_W + 4 * sxx;
            goff[k] = (xx >= 0 && xx + 3 < NN && yy >= 0 && yy < NN)
                          ? (yy * NN + xx) : -1;
        } else {
            sidx[k] = -1;
            goff[k] = -1;
        }
    }

    uint32_t sb[NBUF], pb[NBUF];
#pragma unroll
    for (int b = 0; b < NBUF; b++) {
        sb[b] = (uint32_t)__cvta_generic_to_shared(&sp[b][0][0]);
        pb[b] = (uint32_t)__cvta_generic_to_shared(&pwr[b][0]);
    }

    const bool hasprev = (prev != nullptr);

    // Prologue: groups for planes z0 (slot 0) and z0+1 (slot 1)
    fill_plane(sb[0], cur + z0 * PLANE, goff, sidx);
    fill_pw(pb[0], prev, vp, src, z0 * PLANE + col, hasprev, tid);
    asm volatile("cp.async.commit_group;" ::: "memory");
    fill_plane(sb[1], cur + (z0 + 1) * PLANE, goff, sidx);
    fill_pw(pb[1], prev, vp, src, (z0 + 1) * PLANE + col, hasprev, tid);
    asm volatile("cp.async.commit_group;" ::: "memory");

    // z-queue: 9 named registers, planes z0-4 .. z0+4
    float4 r0, r1, r2, r3, r4, r5, r6, r7, r8;
    {
        float4* rr[9] = {&r0, &r1, &r2, &r3, &r4, &r5, &r6, &r7, &r8};
#pragma unroll
        for (int k = 0; k < 9; k++) {
            int gz = z0 - R + k;
            *rr[k] = (gz >= 0 && gz < NN) ? ldg4(&cur[gz * PLANE + col])
                                          : make_float4(0.f, 0.f, 0.f, 0.f);
        }
    }

    const int sx = R + 4 * tx;
    const int syc = ty + R;

    double acc_s = 0.0;
    float acc_m = 0.0f;

    // 16 unrolled bodies. Consume slot I%3; fill slot (I+2)%3.
    // Queue rotated by argument order (period 9).
#define PB(I, A, B, C, D, E, F, G, H, J)                                      \
    plane_body<FINAL>(cur, prev, vp, src, out, ref,                          \
                      sp[(I) % 3], &pwr[(I) % 3][0],                         \
                      sb[((I) + 2) % 3], pb[((I) + 2) % 3],                  \
                      z0 + (I), hasprev, goff, sidx, col, tid,               \
                      r##A, r##B, r##C, r##D, r##E, r##F, r##G, r##H, r##J,  \
                      sx, syc, acc_s, acc_m)

    PB(0, 0, 1, 2, 3, 4, 5, 6, 7, 8);
    PB(1, 1, 2, 3, 4, 5, 6, 7, 8, 0);
    PB(2, 2, 3, 4, 5, 6, 7, 8, 0, 1);
    PB(3, 3, 4, 5, 6, 7, 8, 0, 1, 2);
    PB(4, 4, 5, 6, 7, 8, 0, 1, 2, 3);
    PB(5, 5, 6, 7, 8, 0, 1, 2, 3, 4);
    PB(6, 6, 7, 8, 0, 1, 2, 3, 4, 5);
    PB(7, 7, 8, 0, 1, 2, 3, 4, 5, 6);
    PB(8, 8, 0, 1, 2, 3, 4, 5, 6, 7);
    PB(9, 0, 1, 2, 3, 4, 5, 6, 7, 8);
    PB(10, 1, 2, 3, 4, 5, 6, 7, 8, 0);
    PB(11, 2, 3, 4, 5, 6, 7, 8, 0, 1);
    PB(12, 3, 4, 5, 6, 7, 8, 0, 1, 2);
    PB(13, 4, 5, 6, 7, 8, 0, 1, 2, 3);
    PB(14, 5, 6, 7, 8, 0, 1, 2, 3, 4);
    PB(15, 6, 7, 8, 0, 1, 2, 3, 4, 5);
#undef PB

    if (FINAL) {
#pragma unroll
        for (int o = 16; o > 0; o >>= 1) {
            acc_s += __shfl_down_sync(0xFFFFFFFFu, acc_s, o);
            acc_m = fmaxf(acc_m, __shfl_down_sync(0xFFFFFFFFu, acc_m, o));
        }
        __shared__ double ss[4];
        __shared__ float sm[4];
        int lane = tid & 31;
        int w = tid >> 5;
        if (lane == 0) { ss[w] = acc_s; sm[w] = acc_m; }
        __syncthreads();
        if (w == 0) {
            acc_s = (lane < 4) ? ss[lane] : 0.0;
            acc_m = (lane < 4) ? sm[lane] : 0.0f;
#pragma unroll
            for (int o = 2; o > 0; o >>= 1) {
                acc_s += __shfl_down_sync(0xFFFFFFFFu, acc_s, o);
                acc_m = fmaxf(acc_m, __shfl_down_sync(0xFFFFFFFFu, acc_m, o));
            }
            if (lane == 0) {
                atomicAdd(&g_sum, acc_s);
                atomicMax(&g_maxbits, __float_as_uint(acc_m));
            }
        }
    }
}

__global__ void finalize_kernel(float* d_out, int n) {
    d_out[0] = (float)(g_sum / (double)n);
    d_out[n + 1] = __uint_as_float(g_maxbits);
}

extern "C" void kernel_launch(void* const* d_in, const int* in_sizes, int n_in,
                              void* d_out, int out_size) {
    const float* vp  = (const float*)d_in[0];
    const float* src = (const float*)d_in[1];
    const float* ref = (const float*)d_in[2];

    static float* bufA = nullptr;
    static float* bufB = nullptr;
    if (!bufA) {
        cudaGetSymbolAddress((void**)&bufA, g_bufA);
        cudaGetSymbolAddress((void**)&bufB, g_bufB);
    }

    const bool has_scalars = (out_size >= VOL + 2);
    float* outp = has_scalars ? ((float*)d_out + 1) : (float*)d_out;

    dim3 blk(TXT, TY);
    dim3 grid(NN / SPANX, NN / TY, NN / ZC);   // (3, 24, 12) = 864 blocks

    init_accum_kernel<<<1, 1>>>();

    const float* s0 = src;

    step_kernel<false><<<grid, blk>>>(s0,   nullptr, vp, src + (size_t)1 * VOL, bufA, nullptr);
    step_kernel<false><<<grid, blk>>>(bufA, s0,      vp, src + (size_t)2 * VOL, bufB, nullptr);
    step_kernel<false><<<grid, blk>>>(bufB, bufA,    vp, src + (size_t)3 * VOL, bufA, nullptr);
    step_kernel<false><<<grid, blk>>>(bufA, bufB,    vp, src + (size_t)4 * VOL, bufB, nullptr);
    step_kernel<false><<<grid, blk>>>(bufB, bufA,    vp, src + (size_t)5 * VOL, bufA, nullptr);
    step_kernel<false><<<grid, blk>>>(bufA, bufB,    vp, src + (size_t)6 * VOL, bufB, nullptr);
    step_kernel<false><<<grid, blk>>>(bufB, bufA,    vp, src + (size_t)7 * VOL, bufA, nullptr);
    step_kernel<false><<<grid, blk>>>(bufA, bufB,    vp, src + (size_t)8 * VOL, bufB, nullptr);
    step_kernel<true><<<grid, blk>>>(bufB, bufA,     vp, src + (size_t)9 * VOL, outp, ref);

    if (has_scalars) {
        finalize_kernel<<<1, 1>>>((float*)d_out, VOL);
    }
}